// round 1
// baseline (speedup 1.0000x reference)
#include <cuda_runtime.h>
#include <math_constants.h>

// ChamferLoss: bidirectional chamfer between pred (16384x3) and gt (16384x3).
// Strategy: min over d2 (sqrt hoisted), ||x||^2 folded out of inner loop,
// packed fma.rn.f32x2 inner loop (2 column points per op), 2 rows per thread.

#define NPTS            16384
#define JCHUNKS         8
#define UNITS_PER_CHUNK 1024          // (NPTS/2) / JCHUNKS
#define ROWS_PER_BLOCK  512
#define THREADS_MAIN    256

typedef unsigned long long ull;

// Packed column data: per unit (2 points j, j+1), 8 floats:
// {-2y0_lo,-2y0_hi, -2y1_lo,-2y1_hi, -2y2_lo,-2y2_hi, |y|^2_lo,|y|^2_hi}
__device__ float4 g_pack[2][NPTS];          // [side][2*unit + k], side 0=pred,1=gt
__device__ float  g_partial[2][JCHUNKS][NPTS];
__device__ float  g_bsum[32];

__device__ __forceinline__ ull pack2(float a, float b) {
    ull r; asm("mov.b64 %0, {%1, %2};" : "=l"(r) : "f"(a), "f"(b)); return r;
}
__device__ __forceinline__ ull fma2(ull a, ull b, ull c) {
    ull d; asm("fma.rn.f32x2 %0, %1, %2, %3;" : "=l"(d) : "l"(a), "l"(b), "l"(c)); return d;
}
__device__ __forceinline__ void unpack2(ull v, float& lo, float& hi) {
    asm("mov.b64 {%0, %1}, %2;" : "=f"(lo), "=f"(hi) : "l"(v));
}

__global__ void pack_kernel(const float* __restrict__ pred,
                            const float* __restrict__ gt) {
    int p = blockIdx.x * blockDim.x + threadIdx.x;   // 0..32767
    int side = p >> 14;
    int idx  = p & (NPTS - 1);
    const float* src = side ? gt : pred;
    float c0 = src[3*idx+0], c1 = src[3*idx+1], c2 = src[3*idx+2];
    float* base = ((float*)&g_pack[side][0]) + (idx >> 1) * 8;
    int lane = idx & 1;
    base[0 + lane] = -2.0f * c0;
    base[2 + lane] = -2.0f * c1;
    base[4 + lane] = -2.0f * c2;
    base[6 + lane] = c0*c0 + c1*c1 + c2*c2;
}

__global__ __launch_bounds__(THREADS_MAIN)
void chamfer_min_kernel(const float* __restrict__ pred,
                        const float* __restrict__ gt) {
    __shared__ ulonglong2 sm[UNITS_PER_CHUNK * 2];   // 32 KB tile

    int b    = blockIdx.x;        // 0..511
    int dir  = b >> 8;            // 0: rows=pred cols=gt, 1: rows=gt cols=pred
    int bb   = b & 255;
    int rowg = bb >> 3;           // 0..31
    int jc   = bb & 7;            // 0..7
    int cs   = dir ^ 1;           // column side

    const float* rowsrc = dir ? gt : pred;

    // Stage this j-chunk's pack data (32 KB) into shared memory.
    const float4* src = &g_pack[cs][jc * (UNITS_PER_CHUNK * 2)];
    float4* dst = (float4*)sm;
    for (int k = threadIdx.x; k < UNITS_PER_CHUNK * 2; k += THREADS_MAIN)
        dst[k] = src[k];
    __syncthreads();

    int r0 = rowg * ROWS_PER_BLOCK + threadIdx.x;
    int r1 = r0 + THREADS_MAIN;
    float a0 = rowsrc[3*r0+0], a1 = rowsrc[3*r0+1], a2 = rowsrc[3*r0+2];
    float c0 = rowsrc[3*r1+0], c1 = rowsrc[3*r1+1], c2 = rowsrc[3*r1+2];
    ull A0 = pack2(a0, a0), A1 = pack2(a1, a1), A2 = pack2(a2, a2);
    ull C0 = pack2(c0, c0), C1 = pack2(c1, c1), C2 = pack2(c2, c2);

    float m0lo = CUDART_INF_F, m0hi = CUDART_INF_F;
    float m1lo = CUDART_INF_F, m1hi = CUDART_INF_F;

    // Inner loop: per unit = 2 column points vs 2 rows = 4 pairs.
    // t = |y|^2 - 2 x.y  (the +|x|^2 is folded out; added in the reduce).
    #pragma unroll 4
    for (int u = 0; u < UNITS_PER_CHUNK; ++u) {
        ulonglong2 q0 = sm[2*u + 0];   // {B0pack, B1pack}
        ulonglong2 q1 = sm[2*u + 1];   // {B2pack, Y2pack}
        ull t0 = fma2(q0.x, A0, fma2(q0.y, A1, fma2(q1.x, A2, q1.y)));
        ull t1 = fma2(q0.x, C0, fma2(q0.y, C1, fma2(q1.x, C2, q1.y)));
        float lo, hi;
        unpack2(t0, lo, hi);
        m0lo = fminf(m0lo, lo); m0hi = fminf(m0hi, hi);
        unpack2(t1, lo, hi);
        m1lo = fminf(m1lo, lo); m1hi = fminf(m1hi, hi);
    }

    g_partial[dir][jc][r0] = fminf(m0lo, m0hi);
    g_partial[dir][jc][r1] = fminf(m1lo, m1hi);
}

__global__ void reduce1_kernel(const float* __restrict__ pred,
                               const float* __restrict__ gt) {
    __shared__ float ssum[1024];
    int bid = blockIdx.x;            // 0..31
    int dir = bid >> 4;
    int blk = bid & 15;
    int i   = blk * 1024 + threadIdx.x;
    const float* rowsrc = dir ? gt : pred;

    float m = CUDART_INF_F;
    #pragma unroll
    for (int c = 0; c < JCHUNKS; ++c) m = fminf(m, g_partial[dir][c][i]);

    float c0 = rowsrc[3*i+0], c1 = rowsrc[3*i+1], c2 = rowsrc[3*i+2];
    float x2 = c0*c0 + c1*c1 + c2*c2;
    float v  = sqrtf(fmaxf(m + x2, 0.0f));

    ssum[threadIdx.x] = v;
    __syncthreads();
    for (int s = 512; s > 0; s >>= 1) {
        if (threadIdx.x < s) ssum[threadIdx.x] += ssum[threadIdx.x + s];
        __syncthreads();
    }
    if (threadIdx.x == 0) g_bsum[bid] = ssum[0];
}

__global__ void reduce2_kernel(float* __restrict__ out) {
    // Deterministic final sum (fixed order), single thread — negligible cost.
    float s = 0.0f;
    #pragma unroll
    for (int k = 0; k < 32; ++k) s += g_bsum[k];
    out[0] = s * (1.0f / 16384.0f);
}

extern "C" void kernel_launch(void* const* d_in, const int* in_sizes, int n_in,
                              void* d_out, int out_size) {
    const float* pred = (const float*)d_in[0];
    const float* gt   = (const float*)d_in[1];
    pack_kernel<<<128, 256>>>(pred, gt);
    chamfer_min_kernel<<<512, 256>>>(pred, gt);
    reduce1_kernel<<<32, 1024>>>(pred, gt);
    reduce2_kernel<<<1, 1>>>((float*)d_out);
}

// round 4
// speedup vs baseline: 1.5849x; 1.5849x over previous
#include <cuda_runtime.h>
#include <math_constants.h>

// ChamferLoss: bidirectional chamfer between pred (16384x3) and gt (16384x3).
// Two-pass row-min formulation: min_j d2 = |x|^2 + min_j(|y|^2 - 2 x.y);
// sqrt hoisted out of inner loop; inner loop = packed fma.rn.f32x2 (2 cols/op)
// against 2 rows per thread. Column pack data staged in smem (broadcast LDS).

#define NPTS            16384
#define JCHUNKS         8
#define CHUNK_PTS       2048           // column points per chunk
#define UNITS_PER_CHUNK 1024           // 2 points per unit
#define ROWS_PER_BLOCK  512
#define THREADS_MAIN    256

typedef unsigned long long ull;

__device__ float g_partial[2][JCHUNKS][NPTS];
__device__ float g_bsum[32];

union F2U { ull u; float2 f; };

__device__ __forceinline__ ull pack2(float a, float b) {
    ull r; asm("mov.b64 %0, {%1, %2};" : "=l"(r) : "f"(a), "f"(b)); return r;
}
__device__ __forceinline__ ull fma2(ull a, ull b, ull c) {
    ull d; asm("fma.rn.f32x2 %0, %1, %2, %3;" : "=l"(d) : "l"(a), "l"(b), "l"(c)); return d;
}

__global__ __launch_bounds__(THREADS_MAIN)
void chamfer_min_kernel(const float* __restrict__ pred,
                        const float* __restrict__ gt) {
    __shared__ ulonglong2 sm[UNITS_PER_CHUNK * 2];   // 32 KB packed column tile

    int b    = blockIdx.x;        // 0..511
    int dir  = b >> 8;            // 0: rows=pred cols=gt ; 1: rows=gt cols=pred
    int bb   = b & 255;
    int rowg = bb >> 3;           // 0..31
    int jc   = bb & 7;            // 0..7

    const float* rowsrc = dir ? gt : pred;
    const float* colsrc = dir ? pred : gt;

    // ---- Stage + pack this chunk's 2048 column points into smem ----
    // Per unit (2 points j,j+1), 8 floats:
    //   {-2y0_lo,-2y0_hi, -2y1_lo,-2y1_hi, -2y2_lo,-2y2_hi, |y|^2_lo,|y|^2_hi}
    {
        int pbase = jc * CHUNK_PTS + threadIdx.x * 8;     // 8 points per thread
        const float4* g4 = (const float4*)(colsrc + 3 * pbase);  // 24 floats, aligned
        float c[24];
        #pragma unroll
        for (int k = 0; k < 6; ++k) {
            float4 v = g4[k];
            c[4*k+0] = v.x; c[4*k+1] = v.y; c[4*k+2] = v.z; c[4*k+3] = v.w;
        }
        float4* smf = (float4*)sm;
        #pragma unroll
        for (int i = 0; i < 4; ++i) {                     // 4 units per thread
            float x0 = c[6*i+0], x1 = c[6*i+1], x2 = c[6*i+2];
            float z0 = c[6*i+3], z1 = c[6*i+4], z2 = c[6*i+5];
            float4 lo, hi;
            lo.x = -2.0f*x0; lo.y = -2.0f*z0;
            lo.z = -2.0f*x1; lo.w = -2.0f*z1;
            hi.x = -2.0f*x2; hi.y = -2.0f*z2;
            hi.z = x0*x0 + x1*x1 + x2*x2;
            hi.w = z0*z0 + z1*z1 + z2*z2;
            int u = threadIdx.x * 4 + i;
            smf[2*u + 0] = lo;
            smf[2*u + 1] = hi;
        }
    }
    __syncthreads();

    // ---- 2 rows per thread ----
    int r0 = rowg * ROWS_PER_BLOCK + threadIdx.x;
    int r1 = r0 + THREADS_MAIN;
    float a0 = __ldg(rowsrc + 3*r0+0), a1 = __ldg(rowsrc + 3*r0+1), a2 = __ldg(rowsrc + 3*r0+2);
    float c0 = __ldg(rowsrc + 3*r1+0), c1 = __ldg(rowsrc + 3*r1+1), c2 = __ldg(rowsrc + 3*r1+2);
    ull A0 = pack2(a0, a0), A1 = pack2(a1, a1), A2 = pack2(a2, a2);
    ull C0 = pack2(c0, c0), C1 = pack2(c1, c1), C2 = pack2(c2, c2);

    float m0lo = CUDART_INF_F, m0hi = CUDART_INF_F;
    float m1lo = CUDART_INF_F, m1hi = CUDART_INF_F;

    // Inner loop: per unit = 2 column points vs 2 rows = 4 pairs.
    // t = |y|^2 - 2 x.y   (the +|x|^2 is folded out; re-added in reduce1).
    #pragma unroll 8
    for (int u = 0; u < UNITS_PER_CHUNK; ++u) {
        ulonglong2 q0 = sm[2*u + 0];   // {B0pack, B1pack}
        ulonglong2 q1 = sm[2*u + 1];   // {B2pack, Y2pack}
        F2U t0, t1;
        t0.u = fma2(q0.x, A0, fma2(q0.y, A1, fma2(q1.x, A2, q1.y)));
        t1.u = fma2(q0.x, C0, fma2(q0.y, C1, fma2(q1.x, C2, q1.y)));
        m0lo = fminf(m0lo, t0.f.x); m0hi = fminf(m0hi, t0.f.y);
        m1lo = fminf(m1lo, t1.f.x); m1hi = fminf(m1hi, t1.f.y);
    }

    g_partial[dir][jc][r0] = fminf(m0lo, m0hi);
    g_partial[dir][jc][r1] = fminf(m1lo, m1hi);
}

__global__ void reduce1_kernel(const float* __restrict__ pred,
                               const float* __restrict__ gt) {
    __shared__ float ssum[1024];
    int bid = blockIdx.x;            // 0..31
    int dir = bid >> 4;
    int blk = bid & 15;
    int i   = blk * 1024 + threadIdx.x;
    const float* rowsrc = dir ? gt : pred;

    float m = CUDART_INF_F;
    #pragma unroll
    for (int c = 0; c < JCHUNKS; ++c) m = fminf(m, g_partial[dir][c][i]);

    float c0 = rowsrc[3*i+0], c1 = rowsrc[3*i+1], c2 = rowsrc[3*i+2];
    float x2 = c0*c0 + c1*c1 + c2*c2;
    float v  = sqrtf(fmaxf(m + x2, 0.0f));

    ssum[threadIdx.x] = v;
    __syncthreads();
    for (int s = 512; s > 0; s >>= 1) {
        if (threadIdx.x < s) ssum[threadIdx.x] += ssum[threadIdx.x + s];
        __syncthreads();
    }
    if (threadIdx.x == 0) g_bsum[bid] = ssum[0];
}

__global__ void reduce2_kernel(float* __restrict__ out) {
    // Deterministic fixed-order final sum; negligible cost.
    float s = 0.0f;
    #pragma unroll
    for (int k = 0; k < 32; ++k) s += g_bsum[k];
    out[0] = s * (1.0f / 16384.0f);
}

extern "C" void kernel_launch(void* const* d_in, const int* in_sizes, int n_in,
                              void* d_out, int out_size) {
    const float* pred = (const float*)d_in[0];
    const float* gt   = (const float*)d_in[1];
    chamfer_min_kernel<<<512, THREADS_MAIN>>>(pred, gt);
    reduce1_kernel<<<32, 1024>>>(pred, gt);
    reduce2_kernel<<<1, 1>>>((float*)d_out);
}